// round 4
// baseline (speedup 1.0000x reference)
#include <cuda_runtime.h>

#define NN 8192
#define EE 524288

// ---------------- scratch (device globals; 16B-aligned; no allocations) ----------------
__device__ __align__(16) float g_deg[NN];
__device__ __align__(16) float g_dinv[NN];
__device__ __align__(16) float g_norm[EE];
__device__ __align__(16) float g_h[NN * 4];   // per-node linear output (h = x @ W.T)
__device__ __align__(16) float g_a[NN * 4];   // conv1 output / conv2 input
__device__ __align__(16) float g_b[NN * 4];   // conv2 output / conv3 input
__device__ __align__(16) float g_x[NN];       // conv3 output == MLP input vector
__device__ __align__(16) float g_y[2 * NN];   // hidden MLP activation

// id -> device buffer (resolved entirely in device code; no host symbol API)
__device__ __forceinline__ float* buf(int id) {
    switch (id) {
        case 0:  return g_h;
        case 1:  return g_a;
        case 2:  return g_b;
        case 3:  return g_x;
        default: return g_y;
    }
}

// ---------------- setup kernels ----------------
__global__ void k_init_deg() {
    int i = blockIdx.x * blockDim.x + threadIdx.x;
    if (i < NN) g_deg[i] = 1.0f;   // self-loop contributes 1 to every node's degree
}

// edge is int32 [2, E] (JAX x64 is disabled, so the "int64" request becomes int32)
__global__ void k_deg(const int* __restrict__ edge) {
    int e = blockIdx.x * blockDim.x + threadIdx.x;
    if (e < EE) atomicAdd(&g_deg[edge[EE + e]], 1.0f);
}

__global__ void k_dinv() {
    int i = blockIdx.x * blockDim.x + threadIdx.x;
    if (i < NN) g_dinv[i] = rsqrtf(g_deg[i]);   // deg >= 1 always (self loop)
}

__global__ void k_norm(const int* __restrict__ edge) {
    int e = blockIdx.x * blockDim.x + threadIdx.x;
    if (e < EE) g_norm[e] = g_dinv[edge[e]] * g_dinv[edge[EE + e]];
}

// ---------------- GCN conv pieces ----------------
// h[i] = in[i] @ W.T ; out[i] initialized with the self-loop term dinv[i]^2 * h[i]
// in_id < 0 means "use the external pointer argument" (conv1 reads harness input).
template <int IC, int OC>
__global__ void k_lin(const float* __restrict__ in_ext, int in_id,
                      const float* __restrict__ W, int out_id) {
    int i = blockIdx.x * blockDim.x + threadIdx.x;
    if (i >= NN) return;
    const float* in = (in_id < 0) ? in_ext : buf(in_id);
    float* h   = g_h;
    float* out = buf(out_id);
    float xi[IC];
#pragma unroll
    for (int c = 0; c < IC; c++) xi[c] = in[i * IC + c];
    float dv = g_dinv[i];
    float dv2 = dv * dv;
#pragma unroll
    for (int oc = 0; oc < OC; oc++) {
        float s = 0.f;
#pragma unroll
        for (int c = 0; c < IC; c++) s = fmaf(xi[c], __ldg(&W[oc * IC + c]), s);
        h[i * OC + oc] = s;
        out[i * OC + oc] = dv2 * s;
    }
}

template <int OC>
__global__ void k_scatter(const int* __restrict__ edge, int out_id) {
    int e = blockIdx.x * blockDim.x + threadIdx.x;
    if (e >= EE) return;
    const float* h = g_h;
    float* out = buf(out_id);
    int s = edge[e];
    int d = edge[EE + e];
    float nm = g_norm[e];
#pragma unroll
    for (int oc = 0; oc < OC; oc++)
        atomicAdd(&out[d * OC + oc], nm * h[s * OC + oc]);
}

template <int OC, bool RELU>
__global__ void k_epi(int out_id, const float* __restrict__ b) {
    int i = blockIdx.x * blockDim.x + threadIdx.x;
    if (i >= NN * OC) return;
    float* out = buf(out_id);
    float v = out[i] + __ldg(&b[i % OC]);
    out[i] = RELU ? fmaxf(v, 0.f) : v;
}

// ---------------- GEMV + tanh: y[row] = tanh(dot(W[row,:], x) + b[row]) ----------------
// x_id selects the device-global input vector; y_id < 0 -> write external y_ext.
__global__ void k_gemv_tanh(const float* __restrict__ W, int x_id,
                            const float* __restrict__ b,
                            float* __restrict__ y_ext, int y_id,
                            int ncols) {
    int row = blockIdx.x;
    const float* x = buf(x_id);
    float* y = (y_id < 0) ? y_ext : buf(y_id);
    int nc4 = ncols >> 2;
    const float4* w4 = reinterpret_cast<const float4*>(W) + (size_t)row * nc4;
    const float4* x4 = reinterpret_cast<const float4*>(x);
    float s = 0.f;
    for (int i = threadIdx.x; i < nc4; i += blockDim.x) {
        float4 a = w4[i];
        float4 c = x4[i];
        s = fmaf(a.x, c.x, s);
        s = fmaf(a.y, c.y, s);
        s = fmaf(a.z, c.z, s);
        s = fmaf(a.w, c.w, s);
    }
#pragma unroll
    for (int off = 16; off; off >>= 1) s += __shfl_down_sync(0xffffffffu, s, off);
    __shared__ float ws[32];
    int lane = threadIdx.x & 31;
    int w = threadIdx.x >> 5;
    if (lane == 0) ws[w] = s;
    __syncthreads();
    if (w == 0) {
        int nw = blockDim.x >> 5;
        s = (lane < nw) ? ws[lane] : 0.f;
#pragma unroll
        for (int off = 16; off; off >>= 1) s += __shfl_down_sync(0xffffffffu, s, off);
        if (lane == 0) y[row] = tanhf(s + __ldg(&b[row]));
    }
}

// ---------------- launch ----------------
extern "C" void kernel_launch(void* const* d_in, const int* in_sizes, int n_in,
                              void* d_out, int out_size) {
    const float* data = (const float*)d_in[0];   // [N,2]
    const int*   edge = (const int*)d_in[1];     // [2,E] int32 (JAX x64 disabled)
    const float* W1 = (const float*)d_in[2];     // [4,2]
    const float* b1 = (const float*)d_in[3];     // [4]
    const float* W2 = (const float*)d_in[4];     // [2,4]
    const float* b2 = (const float*)d_in[5];     // [2]
    const float* W3 = (const float*)d_in[6];     // [1,2]
    const float* b3 = (const float*)d_in[7];     // [1]
    const float* Wa = (const float*)d_in[8];     // [2N, N]
    const float* ba = (const float*)d_in[9];     // [2N]
    const float* Wb = (const float*)d_in[10];    // [32, 2N]
    const float* bb = (const float*)d_in[11];    // [32]
    float* out = (float*)d_out;                  // [1, 32]

    // buffer ids: 0=g_h, 1=g_a, 2=g_b, 3=g_x, 4=g_y
    const int T = 256;
    const int GN = (NN + T - 1) / T;       // 32
    const int GE = (EE + T - 1) / T;       // 2048

    // degree / normalization (edge structure is identical across all 3 convs)
    k_init_deg<<<GN, T>>>();
    k_deg<<<GE, T>>>(edge);
    k_dinv<<<GN, T>>>();
    k_norm<<<GE, T>>>(edge);

    // conv1: [N,2] -> [N,4], relu
    k_lin<2, 4><<<GN, T>>>(data, -1, W1, 1);
    k_scatter<4><<<GE, T>>>(edge, 1);
    k_epi<4, true><<<(NN * 4 + T - 1) / T, T>>>(1, b1);

    // conv2: [N,4] -> [N,2], relu
    k_lin<4, 2><<<GN, T>>>(nullptr, 1, W2, 2);
    k_scatter<2><<<GE, T>>>(edge, 2);
    k_epi<2, true><<<(NN * 2 + T - 1) / T, T>>>(2, b2);

    // conv3: [N,2] -> [N,1], no relu
    k_lin<2, 1><<<GN, T>>>(nullptr, 2, W3, 3);
    k_scatter<1><<<GE, T>>>(edge, 3);
    k_epi<1, false><<<GN, T>>>(3, b3);

    // MLP: tanh(x @ Wa.T + ba) -> tanh(y @ Wb.T + bb)
    k_gemv_tanh<<<2 * NN, 256>>>(Wa, 3, ba, nullptr, 4, NN);
    k_gemv_tanh<<<32, 256>>>(Wb, 4, bb, out, -1, 2 * NN);
}

// round 7
// speedup vs baseline: 1.1139x; 1.1139x over previous
#include <cuda_runtime.h>

#define NN 8192
#define EE 524288

// ---------------- scratch (device globals; 16B-aligned; no allocations) ----------------
__device__ __align__(16) float g_deg[NN];
__device__ __align__(16) float g_dinv[NN];
__device__ __align__(16) float g_norm[EE];
__device__ __align__(16) float g_h[NN * 4];   // per-node linear output (h = x @ W.T)
__device__ __align__(16) float g_a[NN * 4];   // conv1 aggregation (no bias/relu yet)
__device__ __align__(16) float g_b[NN * 4];   // conv2 aggregation (no bias/relu yet)
__device__ __align__(16) float g_x[NN];       // conv3 aggregation (bias folded into GEMV)
__device__ __align__(16) float g_y[2 * NN];   // hidden MLP activation

__device__ __forceinline__ float* buf(int id) {
    switch (id) {
        case 0:  return g_h;
        case 1:  return g_a;
        case 2:  return g_b;
        case 3:  return g_x;
        default: return g_y;
    }
}

// ---------------- setup ----------------
__global__ void k_init_deg() {
    int i = blockIdx.x * blockDim.x + threadIdx.x;
    if (i < NN) g_deg[i] = 1.0f;   // self-loop
}

__global__ void k_deg(const int* __restrict__ edge) {
    int e = blockIdx.x * blockDim.x + threadIdx.x;
    if (e < EE) atomicAdd(&g_deg[edge[EE + e]], 1.0f);
}

__global__ void k_dinv() {
    int i = blockIdx.x * blockDim.x + threadIdx.x;
    if (i < NN) g_dinv[i] = rsqrtf(g_deg[i]);
}

__global__ void k_norm(const int* __restrict__ edge) {
    int e = blockIdx.x * blockDim.x + threadIdx.x;
    if (e < EE) g_norm[e] = g_dinv[edge[e]] * g_dinv[edge[EE + e]];
}

// ---------------- GCN conv pieces ----------------
// h[i] = act(in[i]) @ W.T ; out[i] = dinv[i]^2 * h[i]  (self-loop term)
// If PB != nullptr semantics (pb_valid): act(v) = relu(v + pb[c]) — fuses prev layer epilogue.
template <int IC, int OC, bool FUSE_PREV>
__global__ void k_lin(const float* __restrict__ in_ext, int in_id,
                      const float* __restrict__ pb,
                      const float* __restrict__ W, int out_id) {
    int i = blockIdx.x * blockDim.x + threadIdx.x;
    if (i >= NN) return;
    const float* in = (in_id < 0) ? in_ext : buf(in_id);
    float* h   = g_h;
    float* out = buf(out_id);
    float xi[IC];
#pragma unroll
    for (int c = 0; c < IC; c++) {
        float v = in[i * IC + c];
        if (FUSE_PREV) v = fmaxf(v + __ldg(&pb[c]), 0.f);
        xi[c] = v;
    }
    float dv = g_dinv[i];
    float dv2 = dv * dv;
#pragma unroll
    for (int oc = 0; oc < OC; oc++) {
        float s = 0.f;
#pragma unroll
        for (int c = 0; c < IC; c++) s = fmaf(xi[c], __ldg(&W[oc * IC + c]), s);
        h[i * OC + oc] = s;
        out[i * OC + oc] = dv2 * s;
    }
}

// edge-parallel scatter with vector reductions (sm_90+ red.global.add.vN.f32)
__global__ void k_scatter4(const int* __restrict__ edge, int out_id) {
    int e = blockIdx.x * blockDim.x + threadIdx.x;
    if (e >= EE) return;
    float* out = buf(out_id);
    int s = edge[e];
    int d = edge[EE + e];
    float nm = g_norm[e];
    float4 h = *reinterpret_cast<const float4*>(g_h + 4 * s);
    asm volatile("red.global.add.v4.f32 [%0], {%1, %2, %3, %4};"
                 :: "l"(out + 4 * d),
                    "f"(nm * h.x), "f"(nm * h.y), "f"(nm * h.z), "f"(nm * h.w)
                 : "memory");
}

__global__ void k_scatter2(const int* __restrict__ edge, int out_id) {
    int e = blockIdx.x * blockDim.x + threadIdx.x;
    if (e >= EE) return;
    float* out = buf(out_id);
    int s = edge[e];
    int d = edge[EE + e];
    float nm = g_norm[e];
    float2 h = *reinterpret_cast<const float2*>(g_h + 2 * s);
    asm volatile("red.global.add.v2.f32 [%0], {%1, %2};"
                 :: "l"(out + 2 * d), "f"(nm * h.x), "f"(nm * h.y)
                 : "memory");
}

__global__ void k_scatter1(const int* __restrict__ edge, int out_id) {
    int e = blockIdx.x * blockDim.x + threadIdx.x;
    if (e >= EE) return;
    float* out = buf(out_id);
    atomicAdd(&out[edge[EE + e]], g_norm[e] * g_h[edge[e]]);
}

// ---------------- big GEMV: y[row] = tanh(dot(W[row,:], x + xb) + b[row]) ----------------
// R rows per block: each column chunk of x is read once and reused for R rows,
// cutting x L2 traffic by R. W is streamed with __ldcs (no reuse).
#define GR 8
__global__ void k_gemv_tanh_multi(const float* __restrict__ W, int x_id,
                                  const float* __restrict__ xb,   // scalar bias folded into x (or null)
                                  const float* __restrict__ b,
                                  float* __restrict__ y_ext, int y_id,
                                  int ncols) {
    const float* x = buf(x_id);
    float* y = (y_id < 0) ? y_ext : buf(y_id);
    int row0 = blockIdx.x * GR;
    int nc4 = ncols >> 2;
    float xbv = xb ? __ldg(&xb[0]) : 0.f;
    const float4* x4 = reinterpret_cast<const float4*>(x);

    float acc[GR];
#pragma unroll
    for (int r = 0; r < GR; r++) acc[r] = 0.f;

    for (int i = threadIdx.x; i < nc4; i += blockDim.x) {
        float4 c = x4[i];
        c.x += xbv; c.y += xbv; c.z += xbv; c.w += xbv;
#pragma unroll
        for (int r = 0; r < GR; r++) {
            const float4* w4 = reinterpret_cast<const float4*>(W) + (size_t)(row0 + r) * nc4;
            float4 a = __ldcs(&w4[i]);
            acc[r] = fmaf(a.x, c.x, acc[r]);
            acc[r] = fmaf(a.y, c.y, acc[r]);
            acc[r] = fmaf(a.z, c.z, acc[r]);
            acc[r] = fmaf(a.w, c.w, acc[r]);
        }
    }

    // reduce each accumulator across the warp, then across warps
    int lane = threadIdx.x & 31;
    int w = threadIdx.x >> 5;
#pragma unroll
    for (int r = 0; r < GR; r++)
#pragma unroll
        for (int off = 16; off; off >>= 1)
            acc[r] += __shfl_down_sync(0xffffffffu, acc[r], off);

    __shared__ float part[GR][8];   // blockDim = 256 -> 8 warps
    if (lane == 0)
#pragma unroll
        for (int r = 0; r < GR; r++) part[r][w] = acc[r];
    __syncthreads();
    if (threadIdx.x < GR) {
        float s = 0.f;
#pragma unroll
        for (int ww = 0; ww < 8; ww++) s += part[threadIdx.x][ww];
        int row = row0 + threadIdx.x;
        y[row] = tanhf(s + __ldg(&b[row]));
    }
}

// small GEMV (final layer): one block per row
__global__ void k_gemv_tanh(const float* __restrict__ W, int x_id,
                            const float* __restrict__ b,
                            float* __restrict__ y_ext, int y_id,
                            int ncols) {
    int row = blockIdx.x;
    const float* x = buf(x_id);
    float* y = (y_id < 0) ? y_ext : buf(y_id);
    int nc4 = ncols >> 2;
    const float4* w4 = reinterpret_cast<const float4*>(W) + (size_t)row * nc4;
    const float4* x4 = reinterpret_cast<const float4*>(x);
    float s = 0.f;
    for (int i = threadIdx.x; i < nc4; i += blockDim.x) {
        float4 a = w4[i];
        float4 c = x4[i];
        s = fmaf(a.x, c.x, s);
        s = fmaf(a.y, c.y, s);
        s = fmaf(a.z, c.z, s);
        s = fmaf(a.w, c.w, s);
    }
#pragma unroll
    for (int off = 16; off; off >>= 1) s += __shfl_down_sync(0xffffffffu, s, off);
    __shared__ float ws[32];
    int lane = threadIdx.x & 31;
    int w = threadIdx.x >> 5;
    if (lane == 0) ws[w] = s;
    __syncthreads();
    if (w == 0) {
        int nw = blockDim.x >> 5;
        s = (lane < nw) ? ws[lane] : 0.f;
#pragma unroll
        for (int off = 16; off; off >>= 1) s += __shfl_down_sync(0xffffffffu, s, off);
        if (lane == 0) y[row] = tanhf(s + __ldg(&b[row]));
    }
}

// ---------------- launch ----------------
extern "C" void kernel_launch(void* const* d_in, const int* in_sizes, int n_in,
                              void* d_out, int out_size) {
    const float* data = (const float*)d_in[0];   // [N,2]
    const int*   edge = (const int*)d_in[1];     // [2,E] int32 (JAX x64 disabled)
    const float* W1 = (const float*)d_in[2];     // [4,2]
    const float* b1 = (const float*)d_in[3];     // [4]
    const float* W2 = (const float*)d_in[4];     // [2,4]
    const float* b2 = (const float*)d_in[5];     // [2]
    const float* W3 = (const float*)d_in[6];     // [1,2]
    const float* b3 = (const float*)d_in[7];     // [1]
    const float* Wa = (const float*)d_in[8];     // [2N, N]
    const float* ba = (const float*)d_in[9];     // [2N]
    const float* Wb = (const float*)d_in[10];    // [32, 2N]
    const float* bb = (const float*)d_in[11];    // [32]
    float* out = (float*)d_out;                  // [1, 32]

    // buffer ids: 0=g_h, 1=g_a, 2=g_b, 3=g_x, 4=g_y
    const int T = 256;
    const int GN = (NN + T - 1) / T;       // 32
    const int GE = (EE + T - 1) / T;       // 2048

    // degree / normalization (edge structure identical across all 3 convs)
    k_init_deg<<<GN, T>>>();
    k_deg<<<GE, T>>>(edge);
    k_dinv<<<GN, T>>>();
    k_norm<<<GE, T>>>(edge);

    // conv1: [N,2] -> [N,4]   (bias+relu deferred into lin2)
    k_lin<2, 4, false><<<GN, T>>>(data, -1, nullptr, W1, 1);
    k_scatter4<<<GE, T>>>(edge, 1);

    // conv2: [N,4] -> [N,2]   (applies b1+relu on read; bias+relu deferred into lin3)
    k_lin<4, 2, true><<<GN, T>>>(nullptr, 1, b1, W2, 2);
    k_scatter2<<<GE, T>>>(edge, 2);

    // conv3: [N,2] -> [N,1]   (applies b2+relu on read; b3 folded into the GEMV x-read)
    k_lin<2, 1, true><<<GN, T>>>(nullptr, 2, b2, W3, 3);
    k_scatter1<<<GE, T>>>(edge, 3);

    // MLP: tanh((x+b3) @ Wa.T + ba) -> tanh(y @ Wb.T + bb)
    k_gemv_tanh_multi<<<2 * NN / GR, 256>>>(Wa, 3, b3, ba, nullptr, 4, NN);
    k_gemv_tanh<<<32, 256>>>(Wb, 4, bb, out, -1, 2 * NN);
}